// round 6
// baseline (speedup 1.0000x reference)
#include <cuda_runtime.h>
#include <cuda_bf16.h>
#include <cuda_fp16.h>
#include <cstdint>

// Problem shape (fixed for this dataset variant)
#define NNODES 50000
#define NEDGES 800000
#define IN_DIM 256
#define KHEADS 4
#define FDIM   64
#define KF     256   // KHEADS * FDIM == IN_DIM here

// Scratch (device globals: allocation-free per harness rules)
__device__ __half         g_nodefeat_h[(size_t)NNODES * KF];  // [N, 256] fp16
__device__ float4         g_gauss[NEDGES];                    // [E, 4]
__device__ __nv_bfloat16  g_w_hi[KF * IN_DIM];                // W bf16 hi
__device__ __nv_bfloat16  g_w_lo[KF * IN_DIM];                // W bf16 lo
__device__ __nv_bfloat16  g_a_hi[(size_t)NNODES * IN_DIM];    // A bf16 hi
__device__ __nv_bfloat16  g_a_lo[(size_t)NNODES * IN_DIM];    // A bf16 lo

// ===========================================================================
// Helpers (family-common PTX only: ldmatrix + mma.sync, no tcgen05)
// ===========================================================================
__device__ __forceinline__ uint32_t smem_to_u32(const void* p) {
    uint32_t a;
    asm("{ .reg .u64 t; cvta.to.shared.u64 t, %1; cvt.u32.u64 %0, t; }"
        : "=r"(a) : "l"(p));
    return a;
}

__device__ __forceinline__ void ldmatrix_x4(uint32_t* r, uint32_t addr) {
    asm volatile("ldmatrix.sync.aligned.m8n8.x4.shared.b16 {%0,%1,%2,%3}, [%4];"
        : "=r"(r[0]), "=r"(r[1]), "=r"(r[2]), "=r"(r[3]) : "r"(addr));
}

__device__ __forceinline__ void mma_bf16(float* d, const uint32_t* a,
                                         uint32_t b0, uint32_t b1) {
    asm volatile(
        "mma.sync.aligned.m16n8k16.row.col.f32.bf16.bf16.f32 "
        "{%0,%1,%2,%3}, {%4,%5,%6,%7}, {%8,%9}, {%0,%1,%2,%3};"
        : "+f"(d[0]), "+f"(d[1]), "+f"(d[2]), "+f"(d[3])
        : "r"(a[0]), "r"(a[1]), "r"(a[2]), "r"(a[3]), "r"(b0), "r"(b1));
}

__device__ __forceinline__ uint32_t pack2(__nv_bfloat16 x, __nv_bfloat16 y) {
    uint16_t lo = *(uint16_t*)&x, hi = *(uint16_t*)&y;
    return (uint32_t)lo | ((uint32_t)hi << 16);
}

// ===========================================================================
// One-time fp32 -> bf16 hi/lo splits (W and A), elementwise
// ===========================================================================
__device__ __forceinline__ void split_store(const float4 v,
                                            uint2* hi, uint2* lo, int i)
{
    const float* f = (const float*)&v;
    __nv_bfloat16 h[4], l[4];
#pragma unroll
    for (int q = 0; q < 4; q++) {
        h[q] = __float2bfloat16_rn(f[q]);
        l[q] = __float2bfloat16_rn(f[q] - __bfloat162float(h[q]));
    }
    hi[i] = make_uint2(pack2(h[0], h[1]), pack2(h[2], h[3]));
    lo[i] = make_uint2(pack2(l[0], l[1]), pack2(l[2], l[3]));
}

__global__ void wconv_kernel(const float* __restrict__ W)
{
    const int i = blockIdx.x * blockDim.x + threadIdx.x;   // float4 index
    if (i >= (KF * IN_DIM) / 4) return;
    split_store(((const float4*)W)[i], (uint2*)g_w_hi, (uint2*)g_w_lo, i);
}

__global__ void aconv_kernel(const float* __restrict__ A, int n4)
{
    const int i = blockIdx.x * blockDim.x + threadIdx.x;   // float4 index
    if (i >= n4) return;
    split_store(((const float4*)A)[i], (uint2*)g_a_hi, (uint2*)g_a_lo, i);
}

// ===========================================================================
// Kernel A: bf16 3x-split tensor-core GEMM  C[m,n] = sum_k A[m,k] * W[n,k]
// CTA tile 128x128, K chunked BK=64 (4 chunks). A and W both pre-converted:
// mainloop is pure 16B LDG -> STS -> ldmatrix -> MMA (hh + hl + lh).
// smem rows padded to 72 elems (144 B) -> conflict-free ldmatrix.
// ===========================================================================
#define BK 64
#define LDS_ROW 72                       // elems (144 bytes)
#define TILE_BYTES (128 * LDS_ROW * 2)   // 18432 per hi or lo
#define GEMM_SMEM (4 * TILE_BYTES)       // 73728

__global__ __launch_bounds__(256)
void gemm_mma_kernel(__half* __restrict__ C, int M)
{
    extern __shared__ char smem[];
    const uint32_t sb   = smem_to_u32(smem);
    const uint32_t sA_h = sb;
    const uint32_t sA_l = sb + TILE_BYTES;
    const uint32_t sW_h = sb + 2 * TILE_BYTES;
    const uint32_t sW_l = sb + 3 * TILE_BYTES;

    const int tid  = threadIdx.x;
    const int wid  = tid >> 5;
    const int lane = tid & 31;
    const int m0   = blockIdx.x * 128;
    const int bn   = blockIdx.y * 128;

    const int wm = wid & 1;      // m half (64)
    const int wn = wid >> 1;     // n quarter (32)

    float acc[4][4][4];
#pragma unroll
    for (int i = 0; i < 4; i++)
#pragma unroll
        for (int j = 0; j < 4; j++)
#pragma unroll
            for (int q = 0; q < 4; q++) acc[i][j][q] = 0.0f;

    for (int c = 0; c < IN_DIM / BK; c++) {
        const int kc = c * BK;

        __syncthreads();   // previous chunk's compute readers done

        // ---- A + W: pre-converted bf16, 16B LDG -> STS (1024 uint4 per tensor) ----
#pragma unroll
        for (int j = 0; j < 4; j++) {
            const int id  = tid + j * 256;        // 0..1023
            const int row = id >> 3;              // 0..127
            const int c8  = (id & 7) * 8;         // bf16 col in chunk
            const int gm  = m0 + row;
            const uint32_t off = (uint32_t)(row * (LDS_ROW * 2) + c8 * 2);

            uint4 ah = make_uint4(0, 0, 0, 0), al = make_uint4(0, 0, 0, 0);
            if (gm < M) {
                const size_t aoff = (size_t)gm * IN_DIM + kc + c8;
                ah = *(const uint4*)(g_a_hi + aoff);
                al = *(const uint4*)(g_a_lo + aoff);
            }
            const size_t woff = (size_t)(bn + row) * IN_DIM + kc + c8;
            const uint4 wh = *(const uint4*)(g_w_hi + woff);
            const uint4 wl = *(const uint4*)(g_w_lo + woff);

            asm volatile("st.shared.v4.b32 [%0], {%1,%2,%3,%4};" ::
                "r"(sA_h + off), "r"(ah.x), "r"(ah.y), "r"(ah.z), "r"(ah.w) : "memory");
            asm volatile("st.shared.v4.b32 [%0], {%1,%2,%3,%4};" ::
                "r"(sA_l + off), "r"(al.x), "r"(al.y), "r"(al.z), "r"(al.w) : "memory");
            asm volatile("st.shared.v4.b32 [%0], {%1,%2,%3,%4};" ::
                "r"(sW_h + off), "r"(wh.x), "r"(wh.y), "r"(wh.z), "r"(wh.w) : "memory");
            asm volatile("st.shared.v4.b32 [%0], {%1,%2,%3,%4};" ::
                "r"(sW_l + off), "r"(wl.x), "r"(wl.y), "r"(wl.z), "r"(wl.w) : "memory");
        }
        __syncthreads();

        // ---- compute: 4 k16 steps ----
#pragma unroll
        for (int ks = 0; ks < 4; ks++) {
            const int k16 = ks * 16;
            const uint32_t kbyte = (uint32_t)((k16 + (lane >> 4) * 8) * 2);

            uint32_t a_h[4][4], a_l[4][4];
#pragma unroll
            for (int mt = 0; mt < 4; mt++) {
                const uint32_t roff =
                    (uint32_t)((wm * 64 + mt * 16 + (lane & 15)) * (LDS_ROW * 2)) + kbyte;
                ldmatrix_x4(a_h[mt], sA_h + roff);
                ldmatrix_x4(a_l[mt], sA_l + roff);
            }
            uint32_t b_h[2][4], b_l[2][4];
#pragma unroll
            for (int bg = 0; bg < 2; bg++) {
                const uint32_t roff =
                    (uint32_t)((wn * 32 + bg * 16 + (lane & 15)) * (LDS_ROW * 2)) + kbyte;
                ldmatrix_x4(b_h[bg], sW_h + roff);
                ldmatrix_x4(b_l[bg], sW_l + roff);
            }

#pragma unroll
            for (int mt = 0; mt < 4; mt++) {
#pragma unroll
                for (int nt = 0; nt < 4; nt++) {
                    const int bg = nt >> 1, sel = nt & 1;
                    const uint32_t bh0 = b_h[bg][sel], bh1 = b_h[bg][sel + 2];
                    const uint32_t bl0 = b_l[bg][sel], bl1 = b_l[bg][sel + 2];
                    mma_bf16(acc[mt][nt], a_h[mt], bh0, bh1);   // hh
                    mma_bf16(acc[mt][nt], a_h[mt], bl0, bl1);   // hl
                    mma_bf16(acc[mt][nt], a_l[mt], bh0, bh1);   // lh
                }
            }
        }
    }

    // ---- epilogue: fragment -> gmem fp16 ----
    const int qrow = lane >> 2;
    const int qcol = (lane & 3) * 2;
#pragma unroll
    for (int mt = 0; mt < 4; mt++) {
        const int r0 = m0 + wm * 64 + mt * 16 + qrow;
#pragma unroll
        for (int nt = 0; nt < 4; nt++) {
            const int col = bn + wn * 32 + nt * 8 + qcol;
            if (r0 < M)
                *(__half2*)(C + (size_t)r0 * KF + col) =
                    __floats2half2_rn(acc[mt][nt][0], acc[mt][nt][1]);
            if (r0 + 8 < M)
                *(__half2*)(C + (size_t)(r0 + 8) * KF + col) =
                    __floats2half2_rn(acc[mt][nt][2], acc[mt][nt][3]);
        }
    }
}

// ---------------------------------------------------------------------------
// Kernel B: per-edge gaussian weights  w[e,k] = exp(-0.5 * sum_d ((p-mu)*is)^2)
// ---------------------------------------------------------------------------
__global__ void gauss_kernel(const float* __restrict__ pseudo,
                             const float* __restrict__ mu,
                             const float* __restrict__ inv_sigma,
                             int E)
{
    const int i = blockIdx.x * blockDim.x + threadIdx.x;
    if (i >= E) return;
    const float2 p = *(const float2*)(pseudo + 2 * (size_t)i);

    float w[4];
#pragma unroll
    for (int k = 0; k < 4; k++) {
        const float dx = p.x - mu[2 * k + 0];
        const float dy = p.y - mu[2 * k + 1];
        const float sx = inv_sigma[2 * k + 0];
        const float sy = inv_sigma[2 * k + 1];
        const float t  = dx * dx * sx * sx + dy * dy * sy * sy;
        w[k] = expf(-0.5f * t);
    }
    g_gauss[i] = make_float4(w[0], w[1], w[2], w[3]);
}

// ---------------------------------------------------------------------------
// Kernel C: CSR row-parallel weighted gather + reduce. One warp per row.
// fp16 gathers (half2 per head per lane), fp32 accumulation, 4-edge unroll
// for MLP (16 independent half2 gathers in flight per lane).
// ---------------------------------------------------------------------------
__device__ __forceinline__ void agg_edge(const __half* __restrict__ b,
                                         const float4 w, float& ax, float& ay)
{
    const float2 v0 = __half22float2(*(const __half2*)(b + 0));
    const float2 v1 = __half22float2(*(const __half2*)(b + 64));
    const float2 v2 = __half22float2(*(const __half2*)(b + 128));
    const float2 v3 = __half22float2(*(const __half2*)(b + 192));
    ax = fmaf(w.x, v0.x, ax); ay = fmaf(w.x, v0.y, ay);
    ax = fmaf(w.y, v1.x, ax); ay = fmaf(w.y, v1.y, ay);
    ax = fmaf(w.z, v2.x, ax); ay = fmaf(w.z, v2.y, ay);
    ax = fmaf(w.w, v3.x, ax); ay = fmaf(w.w, v3.y, ay);
}

__global__ void agg_kernel(const int* __restrict__ rowptr,
                           const int* __restrict__ colind,
                           const float* __restrict__ bias,
                           float* __restrict__ out, int N)
{
    const int warp = (blockIdx.x * blockDim.x + threadIdx.x) >> 5;
    const int lane = threadIdx.x & 31;
    if (warp >= N) return;

    const int e0 = rowptr[warp];
    const int e1 = rowptr[warp + 1];

    float ax = 0.f, ay = 0.f;
    const __half* __restrict__ X = g_nodefeat_h;
    const int foff = 2 * lane;

    int e = e0;
    for (; e + 4 <= e1; e += 4) {
        int   s[4];
        float4 w[4];
        const __half* b[4];
#pragma unroll
        for (int q = 0; q < 4; q++) {
            s[q] = colind[e + q];
            w[q] = g_gauss[e + q];
            b[q] = X + (size_t)s[q] * KF + foff;
        }
        // issue all 16 gathers before consuming (compiler front-batches LDGs)
        float2 v[4][4];
#pragma unroll
        for (int q = 0; q < 4; q++) {
            v[q][0] = __half22float2(*(const __half2*)(b[q] + 0));
            v[q][1] = __half22float2(*(const __half2*)(b[q] + 64));
            v[q][2] = __half22float2(*(const __half2*)(b[q] + 128));
            v[q][3] = __half22float2(*(const __half2*)(b[q] + 192));
        }
#pragma unroll
        for (int q = 0; q < 4; q++) {
            ax = fmaf(w[q].x, v[q][0].x, ax); ay = fmaf(w[q].x, v[q][0].y, ay);
            ax = fmaf(w[q].y, v[q][1].x, ax); ay = fmaf(w[q].y, v[q][1].y, ay);
            ax = fmaf(w[q].z, v[q][2].x, ax); ay = fmaf(w[q].z, v[q][2].y, ay);
            ax = fmaf(w[q].w, v[q][3].x, ax); ay = fmaf(w[q].w, v[q][3].y, ay);
        }
    }
    for (; e < e1; e++) {
        agg_edge(X + (size_t)colind[e] * KF + foff, g_gauss[e], ax, ay);
    }

    const float2 b = *(const float2*)(bias + foff);
    *(float2*)(out + (size_t)warp * FDIM + foff) = make_float2(ax + b.x, ay + b.y);
}

// ---------------------------------------------------------------------------
extern "C" void kernel_launch(void* const* d_in, const int* in_sizes, int n_in,
                              void* d_out, int out_size)
{
    const int*   rowptr    = (const int*)d_in[0];
    const int*   colind    = (const int*)d_in[1];
    // d_in[2] colptr, d_in[3] rowind, d_in[4] permute: unused in forward math
    const float* feat      = (const float*)d_in[5];
    const float* pseudo    = (const float*)d_in[6];
    const float* W_fc      = (const float*)d_in[7];
    const float* mu        = (const float*)d_in[8];
    const float* inv_sigma = (const float*)d_in[9];
    const float* bias      = (const float*)d_in[10];
    float*       out       = (float*)d_out;

    const int N = in_sizes[0] - 1;   // 50000
    const int E = in_sizes[1];       // 800000

    __half* nodefeat = nullptr;
    cudaGetSymbolAddress((void**)&nodefeat, g_nodefeat_h);

    // W0/A0: one-time pre-conversion to bf16 hi/lo
    {
        wconv_kernel<<<(KF * IN_DIM / 4 + 255) / 256, 256>>>(W_fc);
        const int n4 = (N * IN_DIM) / 4;
        aconv_kernel<<<(n4 + 255) / 256, 256>>>(feat, n4);
    }
    // A: dense projection feat @ W_fc^T -> g_nodefeat_h [N, 256] fp16
    {
        cudaFuncSetAttribute(gemm_mma_kernel,
                             cudaFuncAttributeMaxDynamicSharedMemorySize, GEMM_SMEM);
        dim3 grid((N + 127) / 128, KF / 128);
        gemm_mma_kernel<<<grid, 256, GEMM_SMEM>>>(nodefeat, N);
    }
    // B: per-edge gaussian weights -> g_gauss [E, 4]
    {
        gauss_kernel<<<(E + 255) / 256, 256>>>(pseudo, mu, inv_sigma, E);
    }
    // C: row-parallel weighted gather + reduce + bias -> out [N, 64]
    {
        const int warps_per_block = 8;
        const int blocks = (N + warps_per_block - 1) / warps_per_block;
        agg_kernel<<<blocks, warps_per_block * 32>>>(rowptr, colind, bias, out, N);
    }
}

// round 7
// speedup vs baseline: 1.1613x; 1.1613x over previous
#include <cuda_runtime.h>
#include <cuda_bf16.h>
#include <cuda_fp16.h>
#include <cstdint>

// Problem shape (fixed for this dataset variant)
#define NNODES 50000
#define NEDGES 800000
#define IN_DIM 256
#define KHEADS 4
#define FDIM   64
#define KF     256   // KHEADS * FDIM == IN_DIM here

// Scratch (device globals: allocation-free per harness rules)
__device__ __half         g_nodefeat_h[(size_t)NNODES * KF];  // [N, 256] fp16
__device__ float4         g_gauss[NEDGES];                    // [E, 4]
__device__ __nv_bfloat16  g_w_hi[KF * IN_DIM];                // W bf16 hi
__device__ __nv_bfloat16  g_w_lo[KF * IN_DIM];                // W bf16 lo

// ===========================================================================
// Helpers (family-common PTX only: ldmatrix + mma.sync, no tcgen05)
// ===========================================================================
__device__ __forceinline__ uint32_t smem_to_u32(const void* p) {
    uint32_t a;
    asm("{ .reg .u64 t; cvta.to.shared.u64 t, %1; cvt.u32.u64 %0, t; }"
        : "=r"(a) : "l"(p));
    return a;
}

__device__ __forceinline__ void ldmatrix_x4(uint32_t* r, uint32_t addr) {
    asm volatile("ldmatrix.sync.aligned.m8n8.x4.shared.b16 {%0,%1,%2,%3}, [%4];"
        : "=r"(r[0]), "=r"(r[1]), "=r"(r[2]), "=r"(r[3]) : "r"(addr));
}

__device__ __forceinline__ void mma_bf16(float* d, const uint32_t* a,
                                         uint32_t b0, uint32_t b1) {
    asm volatile(
        "mma.sync.aligned.m16n8k16.row.col.f32.bf16.bf16.f32 "
        "{%0,%1,%2,%3}, {%4,%5,%6,%7}, {%8,%9}, {%0,%1,%2,%3};"
        : "+f"(d[0]), "+f"(d[1]), "+f"(d[2]), "+f"(d[3])
        : "r"(a[0]), "r"(a[1]), "r"(a[2]), "r"(a[3]), "r"(b0), "r"(b1));
}

__device__ __forceinline__ uint32_t pack2(__nv_bfloat16 x, __nv_bfloat16 y) {
    uint16_t lo = *(uint16_t*)&x, hi = *(uint16_t*)&y;
    return (uint32_t)lo | ((uint32_t)hi << 16);
}

// ===========================================================================
// Kernel W: one-time W pre-conversion fp32 -> bf16 hi/lo (row-major layout)
// ===========================================================================
__global__ void wconv_kernel(const float* __restrict__ W)
{
    const int i = blockIdx.x * blockDim.x + threadIdx.x;   // float4 index
    if (i >= (KF * IN_DIM) / 4) return;
    const float4 v = ((const float4*)W)[i];
    const float* f = (const float*)&v;
    __nv_bfloat16 h[4], l[4];
#pragma unroll
    for (int q = 0; q < 4; q++) {
        h[q] = __float2bfloat16_rn(f[q]);
        l[q] = __float2bfloat16_rn(f[q] - __bfloat162float(h[q]));
    }
    ((uint2*)g_w_hi)[i] = make_uint2(pack2(h[0], h[1]), pack2(h[2], h[3]));
    ((uint2*)g_w_lo)[i] = make_uint2(pack2(l[0], l[1]), pack2(l[2], l[3]));
}

// ===========================================================================
// Kernel A: bf16 3x-split tensor-core GEMM  C[m,n] = sum_k A[m,k] * W[n,k]
// CTA tile 128x128, K chunked BK=64 (4 chunks). A converted in-kernel;
// W loaded pre-converted (bf16 hi/lo). Output written as fp16.
// smem rows padded to 72 elems (144 B) -> conflict-free ldmatrix.
// __launch_bounds__(256, 2): force 2 CTAs/SM (smem 2x73.7KB fits in 228KB,
// regs capped at 128) so one CTA's MMA phase overlaps the other's load phase.
// ===========================================================================
#define BK 64
#define LDS_ROW 72                       // elems (144 bytes)
#define TILE_BYTES (128 * LDS_ROW * 2)   // 18432 per hi or lo
#define GEMM_SMEM (4 * TILE_BYTES)       // 73728

__global__ __launch_bounds__(256, 2)
void gemm_mma_kernel(const float* __restrict__ A, __half* __restrict__ C, int M)
{
    extern __shared__ char smem[];
    const uint32_t sb   = smem_to_u32(smem);
    const uint32_t sA_h = sb;
    const uint32_t sA_l = sb + TILE_BYTES;
    const uint32_t sW_h = sb + 2 * TILE_BYTES;
    const uint32_t sW_l = sb + 3 * TILE_BYTES;

    const int tid  = threadIdx.x;
    const int wid  = tid >> 5;
    const int lane = tid & 31;
    const int m0   = blockIdx.x * 128;
    const int bn   = blockIdx.y * 128;

    const int wm = wid & 1;      // m half (64)
    const int wn = wid >> 1;     // n quarter (32)

    float acc[4][4][4];
#pragma unroll
    for (int i = 0; i < 4; i++)
#pragma unroll
        for (int j = 0; j < 4; j++)
#pragma unroll
            for (int q = 0; q < 4; q++) acc[i][j][q] = 0.0f;

    for (int c = 0; c < IN_DIM / BK; c++) {
        const int kc = c * BK;

        __syncthreads();   // previous chunk's compute readers done

        // ---- A: load fp32, split to bf16 hi/lo, store. 128x64 = 2048 float4 ----
#pragma unroll
        for (int j = 0; j < 8; j++) {
            const int id  = tid + j * 256;
            const int row = id >> 4;
            const int c4  = (id & 15) * 4;
            const int gm  = m0 + row;

            float4 a = (gm < M)
                ? *(const float4*)(A + (size_t)gm * IN_DIM + kc + c4)
                : make_float4(0.f, 0.f, 0.f, 0.f);

            const float* av = (const float*)&a;
            __nv_bfloat16 ah[4], al[4];
#pragma unroll
            for (int q = 0; q < 4; q++) {
                ah[q] = __float2bfloat16_rn(av[q]);
                al[q] = __float2bfloat16_rn(av[q] - __bfloat162float(ah[q]));
            }
            const uint32_t off = (uint32_t)(row * (LDS_ROW * 2) + c4 * 2);
            asm volatile("st.shared.v2.b32 [%0], {%1,%2};" ::
                "r"(sA_h + off), "r"(pack2(ah[0], ah[1])), "r"(pack2(ah[2], ah[3])) : "memory");
            asm volatile("st.shared.v2.b32 [%0], {%1,%2};" ::
                "r"(sA_l + off), "r"(pack2(al[0], al[1])), "r"(pack2(al[2], al[3])) : "memory");
        }
        // ---- W: pre-converted bf16, straight 16B LDG -> STS. 128x64 bf16 ----
#pragma unroll
        for (int j = 0; j < 4; j++) {
            const int id  = tid + j * 256;        // 0..1023
            const int row = id >> 3;              // 0..127
            const int c8  = (id & 7) * 8;         // bf16 col in chunk
            const size_t goff = (size_t)(bn + row) * IN_DIM + kc + c8;
            const uint4 wh = *(const uint4*)(g_w_hi + goff);
            const uint4 wl = *(const uint4*)(g_w_lo + goff);
            const uint32_t off = (uint32_t)(row * (LDS_ROW * 2) + c8 * 2);
            asm volatile("st.shared.v4.b32 [%0], {%1,%2,%3,%4};" ::
                "r"(sW_h + off), "r"(wh.x), "r"(wh.y), "r"(wh.z), "r"(wh.w) : "memory");
            asm volatile("st.shared.v4.b32 [%0], {%1,%2,%3,%4};" ::
                "r"(sW_l + off), "r"(wl.x), "r"(wl.y), "r"(wl.z), "r"(wl.w) : "memory");
        }
        __syncthreads();

        // ---- compute: 4 k16 steps ----
#pragma unroll
        for (int ks = 0; ks < 4; ks++) {
            const int k16 = ks * 16;
            const uint32_t kbyte = (uint32_t)((k16 + (lane >> 4) * 8) * 2);

            uint32_t a_h[4][4], a_l[4][4];
#pragma unroll
            for (int mt = 0; mt < 4; mt++) {
                const uint32_t roff =
                    (uint32_t)((wm * 64 + mt * 16 + (lane & 15)) * (LDS_ROW * 2)) + kbyte;
                ldmatrix_x4(a_h[mt], sA_h + roff);
                ldmatrix_x4(a_l[mt], sA_l + roff);
            }
            uint32_t b_h[2][4], b_l[2][4];
#pragma unroll
            for (int bg = 0; bg < 2; bg++) {
                const uint32_t roff =
                    (uint32_t)((wn * 32 + bg * 16 + (lane & 15)) * (LDS_ROW * 2)) + kbyte;
                ldmatrix_x4(b_h[bg], sW_h + roff);
                ldmatrix_x4(b_l[bg], sW_l + roff);
            }

#pragma unroll
            for (int mt = 0; mt < 4; mt++) {
#pragma unroll
                for (int nt = 0; nt < 4; nt++) {
                    const int bg = nt >> 1, sel = nt & 1;
                    const uint32_t bh0 = b_h[bg][sel], bh1 = b_h[bg][sel + 2];
                    const uint32_t bl0 = b_l[bg][sel], bl1 = b_l[bg][sel + 2];
                    mma_bf16(acc[mt][nt], a_h[mt], bh0, bh1);   // hh
                    mma_bf16(acc[mt][nt], a_h[mt], bl0, bl1);   // hl
                    mma_bf16(acc[mt][nt], a_l[mt], bh0, bh1);   // lh
                }
            }
        }
    }

    // ---- epilogue: fragment -> gmem fp16 ----
    const int qrow = lane >> 2;
    const int qcol = (lane & 3) * 2;
#pragma unroll
    for (int mt = 0; mt < 4; mt++) {
        const int r0 = m0 + wm * 64 + mt * 16 + qrow;
#pragma unroll
        for (int nt = 0; nt < 4; nt++) {
            const int col = bn + wn * 32 + nt * 8 + qcol;
            if (r0 < M)
                *(__half2*)(C + (size_t)r0 * KF + col) =
                    __floats2half2_rn(acc[mt][nt][0], acc[mt][nt][1]);
            if (r0 + 8 < M)
                *(__half2*)(C + (size_t)(r0 + 8) * KF + col) =
                    __floats2half2_rn(acc[mt][nt][2], acc[mt][nt][3]);
        }
    }
}

// ---------------------------------------------------------------------------
// Kernel B: per-edge gaussian weights  w[e,k] = exp(-0.5 * sum_d ((p-mu)*is)^2)
// ---------------------------------------------------------------------------
__global__ void gauss_kernel(const float* __restrict__ pseudo,
                             const float* __restrict__ mu,
                             const float* __restrict__ inv_sigma,
                             int E)
{
    const int i = blockIdx.x * blockDim.x + threadIdx.x;
    if (i >= E) return;
    const float2 p = *(const float2*)(pseudo + 2 * (size_t)i);

    float w[4];
#pragma unroll
    for (int k = 0; k < 4; k++) {
        const float dx = p.x - mu[2 * k + 0];
        const float dy = p.y - mu[2 * k + 1];
        const float sx = inv_sigma[2 * k + 0];
        const float sy = inv_sigma[2 * k + 1];
        const float t  = dx * dx * sx * sx + dy * dy * sy * sy;
        w[k] = expf(-0.5f * t);
    }
    g_gauss[i] = make_float4(w[0], w[1], w[2], w[3]);
}

// ---------------------------------------------------------------------------
// Kernel C: CSR row-parallel weighted gather + reduce. One warp per row.
// fp16 gathers (half2 per head per lane), fp32 accumulation, 2-edge unroll.
// ---------------------------------------------------------------------------
__global__ void agg_kernel(const int* __restrict__ rowptr,
                           const int* __restrict__ colind,
                           const float* __restrict__ bias,
                           float* __restrict__ out, int N)
{
    const int warp = (blockIdx.x * blockDim.x + threadIdx.x) >> 5;
    const int lane = threadIdx.x & 31;
    if (warp >= N) return;

    const int e0 = rowptr[warp];
    const int e1 = rowptr[warp + 1];

    float ax = 0.f, ay = 0.f;
    const __half* __restrict__ X = g_nodefeat_h;
    const int foff = 2 * lane;

    int e = e0;
    for (; e + 2 <= e1; e += 2) {
        const int s0 = colind[e];
        const int s1 = colind[e + 1];
        const float4 w0 = g_gauss[e];
        const float4 w1 = g_gauss[e + 1];
        const __half* b0 = X + (size_t)s0 * KF + foff;
        const __half* b1 = X + (size_t)s1 * KF + foff;
        const float2 v00 = __half22float2(*(const __half2*)(b0 + 0));
        const float2 v01 = __half22float2(*(const __half2*)(b0 + 64));
        const float2 v02 = __half22float2(*(const __half2*)(b0 + 128));
        const float2 v03 = __half22float2(*(const __half2*)(b0 + 192));
        const float2 v10 = __half22float2(*(const __half2*)(b1 + 0));
        const float2 v11 = __half22float2(*(const __half2*)(b1 + 64));
        const float2 v12 = __half22float2(*(const __half2*)(b1 + 128));
        const float2 v13 = __half22float2(*(const __half2*)(b1 + 192));
        ax = fmaf(w0.x, v00.x, ax); ay = fmaf(w0.x, v00.y, ay);
        ax = fmaf(w0.y, v01.x, ax); ay = fmaf(w0.y, v01.y, ay);
        ax = fmaf(w0.z, v02.x, ax); ay = fmaf(w0.z, v02.y, ay);
        ax = fmaf(w0.w, v03.x, ax); ay = fmaf(w0.w, v03.y, ay);
        ax = fmaf(w1.x, v10.x, ax); ay = fmaf(w1.x, v10.y, ay);
        ax = fmaf(w1.y, v11.x, ax); ay = fmaf(w1.y, v11.y, ay);
        ax = fmaf(w1.z, v12.x, ax); ay = fmaf(w1.z, v12.y, ay);
        ax = fmaf(w1.w, v13.x, ax); ay = fmaf(w1.w, v13.y, ay);
    }
    if (e < e1) {
        const int s0 = colind[e];
        const float4 w0 = g_gauss[e];
        const __half* b0 = X + (size_t)s0 * KF + foff;
        const float2 v00 = __half22float2(*(const __half2*)(b0 + 0));
        const float2 v01 = __half22float2(*(const __half2*)(b0 + 64));
        const float2 v02 = __half22float2(*(const __half2*)(b0 + 128));
        const float2 v03 = __half22float2(*(const __half2*)(b0 + 192));
        ax = fmaf(w0.x, v00.x, ax); ay = fmaf(w0.x, v00.y, ay);
        ax = fmaf(w0.y, v01.x, ax); ay = fmaf(w0.y, v01.y, ay);
        ax = fmaf(w0.z, v02.x, ax); ay = fmaf(w0.z, v02.y, ay);
        ax = fmaf(w0.w, v03.x, ax); ay = fmaf(w0.w, v03.y, ay);
    }

    const float2 b = *(const float2*)(bias + foff);
    *(float2*)(out + (size_t)warp * FDIM + foff) = make_float2(ax + b.x, ay + b.y);
}

// ---------------------------------------------------------------------------
extern "C" void kernel_launch(void* const* d_in, const int* in_sizes, int n_in,
                              void* d_out, int out_size)
{
    const int*   rowptr    = (const int*)d_in[0];
    const int*   colind    = (const int*)d_in[1];
    // d_in[2] colptr, d_in[3] rowind, d_in[4] permute: unused in forward math
    const float* feat      = (const float*)d_in[5];
    const float* pseudo    = (const float*)d_in[6];
    const float* W_fc      = (const float*)d_in[7];
    const float* mu        = (const float*)d_in[8];
    const float* inv_sigma = (const float*)d_in[9];
    const float* bias      = (const float*)d_in[10];
    float*       out       = (float*)d_out;

    const int N = in_sizes[0] - 1;   // 50000
    const int E = in_sizes[1];       // 800000

    __half* nodefeat = nullptr;
    cudaGetSymbolAddress((void**)&nodefeat, g_nodefeat_h);

    // W0: one-time W pre-conversion to bf16 hi/lo
    {
        wconv_kernel<<<(KF * IN_DIM / 4 + 255) / 256, 256>>>(W_fc);
    }
    // A: dense projection feat @ W_fc^T -> g_nodefeat_h [N, 256] fp16
    {
        cudaFuncSetAttribute(gemm_mma_kernel,
                             cudaFuncAttributeMaxDynamicSharedMemorySize, GEMM_SMEM);
        dim3 grid((N + 127) / 128, KF / 128);
        gemm_mma_kernel<<<grid, 256, GEMM_SMEM>>>(feat, nodefeat, N);
    }
    // B: per-edge gaussian weights -> g_gauss [E, 4]
    {
        gauss_kernel<<<(E + 255) / 256, 256>>>(pseudo, mu, inv_sigma, E);
    }
    // C: row-parallel weighted gather + reduce + bias -> out [N, 64]
    {
        const int warps_per_block = 8;
        const int blocks = (N + warps_per_block - 1) / warps_per_block;
        agg_kernel<<<blocks, warps_per_block * 32>>>(rowptr, colind, bias, out, N);
    }
}